// round 17
// baseline (speedup 1.0000x reference)
#include <cuda_runtime.h>
#include <cuda_fp16.h>
#include <cstdint>

#define NQ  2048
#define DH  64
#define WIN 512
#define QT  128
// 0.125 * log2(e) folded into Q; softmax in log2 domain via ex2.approx
#define QS2 0.18033688011112042f
#define HONES 0x3C003C00u   // fp16x2 {1.0, 1.0}

// smem byte offsets (total 49152 B -> 2 CTAs/SM at 256 threads)
#define SMB_QH  0        // 128 rows x 32 u32 (fp16x2), word ^ ((row&7)<<2)
#define SMB_KH0 16384    // 64 keys x 32 u32 fp16x2 (same swizzle as QH)
#define SMB_KH1 24576
#define SMB_VH0 32768    // V fp16 row-major [key][d], same swizzle as KH
#define SMB_VH1 40960
#define SMB_TOT 49152

static __device__ __forceinline__ float ex2f(float x) {
    float y; asm("ex2.approx.f32 %0, %1;" : "=f"(y) : "f"(x)); return y;
}
static __device__ __forceinline__ uint32_t packh2(float lo, float hi) {
    __half2 h = __floats2half2_rn(lo, hi);
    return *(uint32_t*)&h;
}
// exp2 of a float pair, computed in packed fp16 (result is an fp16x2 A-frag word)
static __device__ __forceinline__ uint32_t h2exp2(float a, float b) {
    uint32_t p = packh2(a, b);
    uint32_t r; asm("ex2.approx.f16x2 %0, %1;" : "=r"(r) : "r"(p));
    return r;
}
static __device__ __forceinline__ void mma_f16(float* d, const uint32_t* a,
                                               uint32_t b0, uint32_t b1) {
    asm volatile(
        "mma.sync.aligned.m16n8k16.row.col.f32.f16.f16.f32 "
        "{%0,%1,%2,%3}, {%4,%5,%6,%7}, {%8,%9}, {%0,%1,%2,%3};"
        : "+f"(d[0]), "+f"(d[1]), "+f"(d[2]), "+f"(d[3])
        : "r"(a[0]), "r"(a[1]), "r"(a[2]), "r"(a[3]), "r"(b0), "r"(b1));
}
static __device__ __forceinline__ void ldsm_x4(uint32_t* r, uint32_t addr) {
    asm volatile("ldmatrix.sync.aligned.m8n8.x4.shared.b16 {%0,%1,%2,%3}, [%4];"
                 : "=r"(r[0]), "=r"(r[1]), "=r"(r[2]), "=r"(r[3]) : "r"(addr));
}
static __device__ __forceinline__ void ldsm_x4_t(uint32_t* r, uint32_t addr) {
    asm volatile("ldmatrix.sync.aligned.m8n8.x4.trans.shared.b16 {%0,%1,%2,%3}, [%4];"
                 : "=r"(r[0]), "=r"(r[1]), "=r"(r[2]), "=r"(r[3]) : "r"(addr));
}
static __device__ __forceinline__ uint32_t smem_u32(const void* p) {
    uint32_t a;
    asm("{ .reg .u64 t; cvta.to.shared.u64 t, %1; cvt.u32.u64 %0, t; }" : "=r"(a) : "l"(p));
    return a;
}

__global__ __launch_bounds__(256, 2)
void swa_mma_kernel(const float* __restrict__ q, const float* __restrict__ k,
                    const float* __restrict__ v, float* __restrict__ out)
{
    extern __shared__ char smc[];
    const uint32_t sb = smem_u32(smc);
    uint32_t* Qh = (uint32_t*)(smc + SMB_QH);

    const int tid  = threadIdx.x;
    const int w    = tid >> 5;       // 0..7, one m16 tile each
    const int lane = tid & 31;
    const int gid  = lane >> 2;
    const int tig  = lane & 3;

    const int qt2 = (int)gridDim.x - 1 - (int)blockIdx.x;   // long CTAs first
    const int bh  = blockIdx.y;
    const int qs  = qt2 * QT;

    const float* qp = q + (size_t)bh * NQ * DH;
    const float* kp = k + (size_t)bh * NQ * DH;
    const float* vp = v + (size_t)bh * NQ * DH;

    const int kt_lo = (2 * qt2 - 8) > 0 ? (2 * qt2 - 8) : 0;
    const int kt_hi = 2 * qt2 + 1;

    // converted-tile cell ownership (prefetch-LDG and STS use the same map)
    const int sc  = tid & 15;        // 16B col-chunk
    const int sk0 = tid >> 4;        // base key

    // ---- ldmatrix per-lane address components (word units) ----
    const int ls2    = (lane & 7) << 2;                                   // swizzle term
    const int qrow32 = (16 * w + (lane & 7) + 8 * ((lane >> 3) & 1)) * 32;
    const int qch    = 4 * (lane >> 4);                                   // a0/a2 half
    const int krow32 = (8 * (lane >> 4) + (lane & 7)) * 32;               // key within 16-key grp
    const int kch    = 4 * ((lane >> 3) & 1);                             // b0/b1 half
    const int vk32   = (8 * ((lane >> 3) & 1) + (lane & 7)) * 32;
    const int vch    = 4 * (lane >> 4);

    // ---- prologue: tile kt_lo direct LDG->pack->STS, stage Q ----
    {
        const float* kg = kp + (size_t)kt_lo * 64 * DH;
        const float* vg = vp + (size_t)kt_lo * 64 * DH;
        uint32_t* KHd = (uint32_t*)(smc + SMB_KH0);
        uint32_t* VHd = (uint32_t*)(smc + SMB_VH0);
#pragma unroll
        for (int it = 0; it < 4; it++) {
            int key = sk0 + 16 * it;
            float4 t = *(const float4*)(kg + key * DH + 4 * sc);
            float4 u = *(const float4*)(vg + key * DH + 4 * sc);
            uint2 wv; wv.x = packh2(t.x, t.y); wv.y = packh2(t.z, t.w);
            *(uint2*)(KHd + key * 32 + ((2 * sc) ^ ((key & 7) << 2))) = wv;
            uint2 wu; wu.x = packh2(u.x, u.y); wu.y = packh2(u.z, u.w);
            *(uint2*)(VHd + key * 32 + ((2 * sc) ^ ((key & 7) << 2))) = wu;
        }
    }
#pragma unroll
    for (int i = tid; i < 2048; i += 256) {
        int row = i >> 4, c = i & 15;
        float4 t = *(const float4*)(qp + (size_t)(qs + row) * DH + 4 * c);
        uint2 wv;
        wv.x = packh2(t.x * QS2, t.y * QS2);
        wv.y = packh2(t.z * QS2, t.w * QS2);
        *(uint2*)(Qh + row * 32 + ((2 * c) ^ ((row & 7) << 2))) = wv;
    }
    __syncthreads();

    float o[8][4];
#pragma unroll
    for (int db = 0; db < 8; db++)
#pragma unroll
        for (int j = 0; j < 4; j++) o[db][j] = 0.f;
    float mh[2] = {-1e30f, -1e30f};
    float lh[2] = {0.f, 0.f};

    int x = 0;
    for (int kt = kt_lo; kt <= kt_hi; kt++) {
        const uint32_t KHb = sb + (x ? SMB_KH1 : SMB_KH0);
        const uint32_t VHb = sb + (x ? SMB_VH1 : SMB_VH0);
        uint32_t* KHd = (uint32_t*)(smc + (x ? SMB_KH0 : SMB_KH1));
        uint32_t* VHd = (uint32_t*)(smc + (x ? SMB_VH0 : SMB_VH1));

        // ---- issue register prefetch of tile kt+1 (latency covered by compute) ----
        const bool havenext = (kt + 1 <= kt_hi);
        float4 kf[4], vf[4];
        if (havenext) {
            const float* kg = kp + (size_t)(kt + 1) * 64 * DH;
            const float* vg = vp + (size_t)(kt + 1) * 64 * DH;
#pragma unroll
            for (int it = 0; it < 4; it++) {
                int key = sk0 + 16 * it;
                kf[it] = *(const float4*)(kg + key * DH + 4 * sc);
                vf[it] = *(const float4*)(vg + key * DH + 4 * sc);
            }
        }

        // warp fully-masked tile skip
        const bool skip = (kt == 2 * qt2 + 1 && w < 4) || (kt == 2 * qt2 - 8 && w >= 4);

        float s[8][4];
        uint32_t ap[4][4];
        if (!skip) {
            // ---- S = Q·K^T (fp16 m16n8k16, ldmatrix operands) ----
#pragma unroll
            for (int nb = 0; nb < 8; nb++)
#pragma unroll
                for (int j = 0; j < 4; j++) s[nb][j] = 0.f;
#pragma unroll
            for (int ks = 0; ks < 4; ks++) {
                uint32_t a0[4];
                ldsm_x4(a0, sb + SMB_QH + 4u * (uint32_t)(qrow32 + ((8 * ks + qch) ^ ls2)));
                uint32_t b[16];
#pragma unroll
                for (int g = 0; g < 4; g++)
                    ldsm_x4(b + 4 * g,
                            KHb + 4u * (uint32_t)(krow32 + g * 512 + ((8 * ks + kch) ^ ls2)));
#pragma unroll
                for (int g = 0; g < 4; g++) {
                    mma_f16(s[2 * g],     a0, b[4 * g],     b[4 * g + 1]);
                    mma_f16(s[2 * g + 1], a0, b[4 * g + 2], b[4 * g + 3]);
                }
            }

            // ---- boundary masks ----
            const bool do_mask = (kt == 2 * qt2 - 8) || (kt == 2 * qt2 - 7) ||
                                 (kt == 2 * qt2 && w < 4) || (kt == 2 * qt2 + 1);
            if (do_mask) {
#pragma unroll
                for (int nb = 0; nb < 8; nb++)
#pragma unroll
                    for (int j = 0; j < 4; j++) {
                        int cg = kt * 64 + nb * 8 + 2 * tig + (j & 1);
                        int rg = qs + 16 * w + gid + 8 * (j >> 1);
                        if (cg > rg || cg < rg - (WIN - 1)) s[nb][j] = -1e30f;
                    }
            }

            // ---- online softmax: f32 max trees, fp16x2 exp ----
            float mx[2], corr[2];
#pragma unroll
            for (int u = 0; u < 2; u++) {
                float m0 = fmaxf(s[0][2 * u], s[0][2 * u + 1]);
                float m1 = fmaxf(s[1][2 * u], s[1][2 * u + 1]);
                float m2 = fmaxf(s[2][2 * u], s[2][2 * u + 1]);
                float m3 = fmaxf(s[3][2 * u], s[3][2 * u + 1]);
                float m4 = fmaxf(s[4][2 * u], s[4][2 * u + 1]);
                float m5 = fmaxf(s[5][2 * u], s[5][2 * u + 1]);
                float m6 = fmaxf(s[6][2 * u], s[6][2 * u + 1]);
                float m7 = fmaxf(s[7][2 * u], s[7][2 * u + 1]);
                mx[u] = fmaxf(fmaxf(fmaxf(m0, m1), fmaxf(m2, m3)),
                              fmaxf(fmaxf(m4, m5), fmaxf(m6, m7)));
            }
#pragma unroll
            for (int u = 0; u < 2; u++) mx[u] = fmaxf(mx[u], __shfl_xor_sync(0xffffffffu, mx[u], 1));
#pragma unroll
            for (int u = 0; u < 2; u++) mx[u] = fmaxf(mx[u], __shfl_xor_sync(0xffffffffu, mx[u], 2));
#pragma unroll
            for (int u = 0; u < 2; u++) {
                float mn = fmaxf(mh[u], mx[u]);
                corr[u] = ex2f(mh[u] - mn);
                mh[u] = mn;
            }
#pragma unroll
            for (int u = 0; u < 2; u++)
#pragma unroll
                for (int db = 0; db < 8; db++) {
                    o[db][2 * u]     *= corr[u];
                    o[db][2 * u + 1] *= corr[u];
                }
#pragma unroll
            for (int j = 0; j < 4; j++) {
                ap[j][0] = h2exp2(s[2 * j][0]     - mh[0], s[2 * j][1]     - mh[0]);
                ap[j][1] = h2exp2(s[2 * j][2]     - mh[1], s[2 * j][3]     - mh[1]);
                ap[j][2] = h2exp2(s[2 * j + 1][0] - mh[0], s[2 * j + 1][1] - mh[0]);
                ap[j][3] = h2exp2(s[2 * j + 1][2] - mh[1], s[2 * j + 1][3] - mh[1]);
            }
            lh[0] *= corr[0];
            lh[1] *= corr[1];
        }

        // ---- pack+STS K(kt+1) here: kf dies before PV, LDG latency already covered ----
        if (havenext) {
#pragma unroll
            for (int it = 0; it < 4; it++) {
                int key = sk0 + 16 * it;
                uint2 wv;
                wv.x = packh2(kf[it].x, kf[it].y);
                wv.y = packh2(kf[it].z, kf[it].w);
                *(uint2*)(KHd + key * 32 + ((2 * sc) ^ ((key & 7) << 2))) = wv;
            }
        }

        if (!skip) {
            // ---- O += P·V  and  l += P·1 ----
            float lsum[4] = {0.f, 0.f, 0.f, 0.f};
#pragma unroll
            for (int j = 0; j < 4; j++) {
#pragma unroll
                for (int g = 0; g < 4; g++) {
                    uint32_t rv[4];
                    ldsm_x4_t(rv, VHb + 4u * (uint32_t)(j * 512 + vk32 + ((8 * g + vch) ^ ls2)));
                    mma_f16(o[2 * g],     ap[j], rv[0], rv[1]);
                    mma_f16(o[2 * g + 1], ap[j], rv[2], rv[3]);
                }
                mma_f16(lsum, ap[j], HONES, HONES);
            }
            lh[0] += lsum[0];
            lh[1] += lsum[2];
        }

        // ---- pack+STS V(kt+1) ----
        if (havenext) {
#pragma unroll
            for (int it = 0; it < 4; it++) {
                int key = sk0 + 16 * it;
                uint2 wu;
                wu.x = packh2(vf[it].x, vf[it].y);
                wu.y = packh2(vf[it].z, vf[it].w);
                *(uint2*)(VHd + key * 32 + ((2 * sc) ^ ((key & 7) << 2))) = wu;
            }
        }

        __syncthreads();    // publish converted buf, retire current buf
        x ^= 1;
    }

    // ---- epilogue ----
    {
        const int rl0 = 16 * w + gid;
        float inv0 = 1.0f / lh[0];
        float inv1 = 1.0f / lh[1];
        float* op = out + ((size_t)bh * NQ + qs + rl0) * DH;
#pragma unroll
        for (int db = 0; db < 8; db++) {
            *(float2*)(op + db * 8 + 2 * tig) =
                make_float2(o[db][0] * inv0, o[db][1] * inv0);
            *(float2*)(op + 8 * DH + db * 8 + 2 * tig) =
                make_float2(o[db][2] * inv1, o[db][3] * inv1);
        }
    }
}

extern "C" void kernel_launch(void* const* d_in, const int* in_sizes, int n_in,
                              void* d_out, int out_size)
{
    const float* q = (const float*)d_in[0];
    const float* k = (const float*)d_in[1];
    const float* v = (const float*)d_in[2];
    float* o = (float*)d_out;

    cudaFuncSetAttribute(swa_mma_kernel, cudaFuncAttributeMaxDynamicSharedMemorySize, SMB_TOT);
    dim3 grid(NQ / QT, 32);   // (16 query tiles, B*H)
    swa_mma_kernel<<<grid, 256, SMB_TOT>>>(q, k, v, o);
}